// round 7
// baseline (speedup 1.0000x reference)
#include <cuda_runtime.h>
#include <math.h>

#define NODES 100000
#define EMAX  1600000
#define SCAN_CHUNK 2048
#define SCAN_NB ((NODES + SCAN_CHUNK - 1) / SCAN_CHUNK)   // 49

// ---------------- device scratch ------------------------------------------------
__device__ int   g_deg[NODES];
__device__ int   g_cur[NODES];
__device__ int   g_rowptr[NODES + 1];
__device__ int   g_col[EMAX];
__device__ int   g_blocksum[SCAN_NB];
__device__ int   g_blockoff[SCAN_NB];
__device__ float g_dinv[NODES];
__device__ float g_bufA[(size_t)NODES * 64];
__device__ float g_bufB[(size_t)NODES * 64];
__device__ float g_buf128[(size_t)NODES * 128];

__device__ __forceinline__ float elu_f(float x) { return x > 0.f ? x : expm1f(x); }

__device__ __forceinline__ unsigned tf32_of(float x) {
    unsigned r; asm("cvt.rna.tf32.f32 %0, %1;" : "=r"(r) : "f"(x)); return r;
}
__device__ __forceinline__ void split_tf32(float x, unsigned& hi, unsigned& lo) {
    hi = tf32_of(x);
    lo = tf32_of(x - __uint_as_float(hi));
}
__device__ __forceinline__ void mma8(float* c,
    unsigned a0, unsigned a1, unsigned a2, unsigned a3, unsigned b0, unsigned b1)
{
    asm volatile(
        "mma.sync.aligned.m16n8k8.row.col.f32.tf32.tf32.f32 "
        "{%0,%1,%2,%3},{%4,%5,%6,%7},{%8,%9},{%0,%1,%2,%3};"
        : "+f"(c[0]), "+f"(c[1]), "+f"(c[2]), "+f"(c[3])
        : "r"(a0), "r"(a1), "r"(a2), "r"(a3), "r"(b0), "r"(b1));
}

// ---------------- CSR build (edge_index is int32) ------------------------------
__global__ void zero_kernel(int n) {
    int i = blockIdx.x * blockDim.x + threadIdx.x;
    if (i < n) { g_deg[i] = 0; g_cur[i] = 0; }
}

__global__ void count_kernel(const int* __restrict__ ei, int E, int n) {
    int e = blockIdx.x * blockDim.x + threadIdx.x;
    if (e < E) {
        int d = ei[E + e];
        if ((unsigned)d < (unsigned)n) atomicAdd(&g_deg[d], 1);
    }
}

__global__ __launch_bounds__(256) void scan_reduce(int n) {
    int b = blockIdx.x, t = threadIdx.x;
    int base = b * SCAN_CHUNK + t * 8;
    int s = 0;
#pragma unroll
    for (int i = 0; i < 8; i++) {
        int idx = base + i;
        if (idx < n) s += g_deg[idx];
    }
#pragma unroll
    for (int off = 16; off; off >>= 1)
        s += __shfl_down_sync(0xffffffffu, s, off);
    __shared__ int wsum[8];
    if ((t & 31) == 0) wsum[t >> 5] = s;
    __syncthreads();
    if (t == 0) {
        int tot = 0;
#pragma unroll
        for (int w = 0; w < 8; w++) tot += wsum[w];
        g_blocksum[b] = tot;
    }
}

__global__ void scan_spine(int n, int nb) {
    int run = 0;
    for (int b = 0; b < nb; b++) { g_blockoff[b] = run; run += g_blocksum[b]; }
    g_rowptr[n] = run;
}

__global__ __launch_bounds__(256) void scan_apply(int n) {
    int b = blockIdx.x, t = threadIdx.x;
    int lane = t & 31, wid = t >> 5;
    int base = b * SCAN_CHUNK + t * 8;
    int v[8]; int s = 0;
#pragma unroll
    for (int i = 0; i < 8; i++) {
        int idx = base + i;
        v[i] = (idx < n) ? g_deg[idx] : 0;
        s += v[i];
    }
    int inc = s;
#pragma unroll
    for (int off = 1; off < 32; off <<= 1) {
        int u = __shfl_up_sync(0xffffffffu, inc, off);
        if (lane >= off) inc += u;
    }
    __shared__ int wsum[8];
    if (lane == 31) wsum[wid] = inc;
    __syncthreads();
    int woff = 0;
    for (int w = 0; w < wid; w++) woff += wsum[w];
    int run = g_blockoff[b] + woff + (inc - s);
#pragma unroll
    for (int i = 0; i < 8; i++) {
        int idx = base + i;
        if (idx < n) {
            g_rowptr[idx] = run;
            g_dinv[idx] = rsqrtf((float)v[i] + 1.0f);
        }
        run += v[i];
    }
}

__global__ void fill_kernel(const int* __restrict__ ei, int E, int n) {
    int e = blockIdx.x * blockDim.x + threadIdx.x;
    if (e < E) {
        int s = ei[e];
        int d = ei[E + e];
        if ((unsigned)s < (unsigned)n && (unsigned)d < (unsigned)n) {
            int pos = g_rowptr[d] + atomicAdd(&g_cur[d], 1);
            g_col[pos] = s;
        }
    }
}

// ---------------- tf32 GEMM: [N,128]@[128,64], out *= dinv[row] ----------------
// 128 threads (4 warps), 64-node tile, warp owns 16 rows; 3xTF32 for fp32 accuracy
template <bool FIRST>
__global__ __launch_bounds__(128) void gemm_tf32_k128n64(
    const float* __restrict__ Xin, const float* __restrict__ W, int n)
{
    const float* __restrict__ X = FIRST ? Xin : (const float*)g_buf128;
    float* __restrict__ out = FIRST ? g_bufA : g_bufB;

    __shared__ unsigned Wh[32 * 64], Wl[32 * 64];  // 16 KB
    __shared__ float Xs[64 * 36];                  // 9.2 KB
    int tid = threadIdx.x, lane = tid & 31, w = tid >> 5;
    int n0 = blockIdx.x * 64;
    int rA = w * 16 + (lane >> 2);
    int ca = lane & 3;

    float acc[8][4];
#pragma unroll
    for (int i = 0; i < 8; i++)
#pragma unroll
        for (int j = 0; j < 4; j++) acc[i][j] = 0.f;

    for (int kc0 = 0; kc0 < 128; kc0 += 32) {
        __syncthreads();
        for (int i = tid; i < 32 * 64; i += 128) {
            float wv = W[(kc0 + (i >> 6)) * 64 + (i & 63)];
            unsigned h, l; split_tf32(wv, h, l);
            Wh[i] = h; Wl[i] = l;
        }
        for (int i = tid; i < 64 * 8; i += 128) {
            int node = i >> 3, kc = (i & 7) << 2;
            float4 v = make_float4(0.f, 0.f, 0.f, 0.f);
            if (n0 + node < n)
                v = *(const float4*)(X + (size_t)(n0 + node) * 128 + kc0 + kc);
            *(float4*)(Xs + node * 36 + kc) = v;
        }
        __syncthreads();
#pragma unroll
        for (int ks = 0; ks < 4; ks++) {
            int kb = ks * 8;
            unsigned ah[4], al[4];
            split_tf32(Xs[rA * 36 + kb + ca],           ah[0], al[0]);
            split_tf32(Xs[(rA + 8) * 36 + kb + ca],     ah[1], al[1]);
            split_tf32(Xs[rA * 36 + kb + ca + 4],       ah[2], al[2]);
            split_tf32(Xs[(rA + 8) * 36 + kb + ca + 4], ah[3], al[3]);
#pragma unroll
            for (int nt = 0; nt < 8; nt++) {
                int col = nt * 8 + (lane >> 2);
                int i0 = (kb + ca) * 64 + col;
                int i1 = (kb + ca + 4) * 64 + col;
                unsigned bh0 = Wh[i0], bh1 = Wh[i1];
                unsigned bl0 = Wl[i0], bl1 = Wl[i1];
                mma8(acc[nt], ah[0], ah[1], ah[2], ah[3], bh0, bh1);
                mma8(acc[nt], ah[0], ah[1], ah[2], ah[3], bl0, bl1);
                mma8(acc[nt], al[0], al[1], al[2], al[3], bh0, bh1);
            }
        }
    }
    int rowa = n0 + rA, rowb = rowa + 8;
    float dva = (rowa < n) ? g_dinv[rowa] : 0.f;
    float dvb = (rowb < n) ? g_dinv[rowb] : 0.f;
#pragma unroll
    for (int nt = 0; nt < 8; nt++) {
        int col = nt * 8 + 2 * (lane & 3);
        if (rowa < n) {
            float2 o = make_float2(acc[nt][0] * dva, acc[nt][1] * dva);
            *(float2*)(out + (size_t)rowa * 64 + col) = o;
        }
        if (rowb < n) {
            float2 o = make_float2(acc[nt][2] * dvb, acc[nt][3] * dvb);
            *(float2*)(out + (size_t)rowb * 64 + col) = o;
        }
    }
}

// ---------------- tf32 GEMM2: g_bufA[N,64]@[64,128] + b -> LN -> ELU -> g_buf128
__global__ __launch_bounds__(128) void gemm2_tf32(
    const float* __restrict__ W, const float* __restrict__ b,
    const float* __restrict__ g, const float* __restrict__ be, int n)
{
    const float* __restrict__ S = (const float*)g_bufA;
    float* __restrict__ out = g_buf128;

    __shared__ unsigned Wh[32 * 128], Wl[32 * 128];  // 32 KB
    __shared__ float Xs[64 * 36];                    // 9.2 KB
    __shared__ float sb[128], sg[128], sbe[128];
    int tid = threadIdx.x, lane = tid & 31, w = tid >> 5;
    if (tid < 128) { sb[tid] = b[tid]; sg[tid] = g[tid]; sbe[tid] = be[tid]; }
    int n0 = blockIdx.x * 64;
    int rA = w * 16 + (lane >> 2);
    int ca = lane & 3;

    float acc[16][4];
#pragma unroll
    for (int i = 0; i < 16; i++)
#pragma unroll
        for (int j = 0; j < 4; j++) acc[i][j] = 0.f;

    for (int kc0 = 0; kc0 < 64; kc0 += 32) {
        __syncthreads();
        for (int i = tid; i < 32 * 128; i += 128) {
            float wv = W[(kc0 + (i >> 7)) * 128 + (i & 127)];
            unsigned h, l; split_tf32(wv, h, l);
            Wh[i] = h; Wl[i] = l;
        }
        for (int i = tid; i < 64 * 8; i += 128) {
            int node = i >> 3, kc = (i & 7) << 2;
            float4 v = make_float4(0.f, 0.f, 0.f, 0.f);
            if (n0 + node < n)
                v = *(const float4*)(S + (size_t)(n0 + node) * 64 + kc0 + kc);
            *(float4*)(Xs + node * 36 + kc) = v;
        }
        __syncthreads();
#pragma unroll
        for (int ks = 0; ks < 4; ks++) {
            int kb = ks * 8;
            unsigned ah[4], al[4];
            split_tf32(Xs[rA * 36 + kb + ca],           ah[0], al[0]);
            split_tf32(Xs[(rA + 8) * 36 + kb + ca],     ah[1], al[1]);
            split_tf32(Xs[rA * 36 + kb + ca + 4],       ah[2], al[2]);
            split_tf32(Xs[(rA + 8) * 36 + kb + ca + 4], ah[3], al[3]);
#pragma unroll
            for (int nt = 0; nt < 16; nt++) {
                int col = nt * 8 + (lane >> 2);
                int i0 = (kb + ca) * 128 + col;
                int i1 = (kb + ca + 4) * 128 + col;
                unsigned bh0 = Wh[i0], bh1 = Wh[i1];
                unsigned bl0 = Wl[i0], bl1 = Wl[i1];
                mma8(acc[nt], ah[0], ah[1], ah[2], ah[3], bh0, bh1);
                mma8(acc[nt], ah[0], ah[1], ah[2], ah[3], bl0, bl1);
                mma8(acc[nt], al[0], al[1], al[2], al[3], bh0, bh1);
            }
        }
    }

    // epilogue: bias + LN(128) + ELU; row owned by a lane-quad
    int rowa = n0 + rA, rowb = rowa + 8;
    float sa = 0.f, qa = 0.f, sbv = 0.f, qb = 0.f;
#pragma unroll
    for (int nt = 0; nt < 16; nt++) {
        int col = nt * 8 + 2 * (lane & 3);
        float v0 = acc[nt][0] + sb[col], v1 = acc[nt][1] + sb[col + 1];
        float v2 = acc[nt][2] + sb[col], v3 = acc[nt][3] + sb[col + 1];
        sa += v0 + v1; qa += v0 * v0 + v1 * v1;
        sbv += v2 + v3; qb += v2 * v2 + v3 * v3;
    }
#pragma unroll
    for (int off = 1; off <= 2; off <<= 1) {
        sa  += __shfl_xor_sync(0xffffffffu, sa,  off);
        qa  += __shfl_xor_sync(0xffffffffu, qa,  off);
        sbv += __shfl_xor_sync(0xffffffffu, sbv, off);
        qb  += __shfl_xor_sync(0xffffffffu, qb,  off);
    }
    float mua = sa * (1.f / 128.f);
    float ra = rsqrtf(qa * (1.f / 128.f) - mua * mua + 1e-5f);
    float mub = sbv * (1.f / 128.f);
    float rb = rsqrtf(qb * (1.f / 128.f) - mub * mub + 1e-5f);
#pragma unroll
    for (int nt = 0; nt < 16; nt++) {
        int col = nt * 8 + 2 * (lane & 3);
        if (rowa < n) {
            float2 o;
            o.x = elu_f((acc[nt][0] + sb[col]     - mua) * ra * sg[col]     + sbe[col]);
            o.y = elu_f((acc[nt][1] + sb[col + 1] - mua) * ra * sg[col + 1] + sbe[col + 1]);
            *(float2*)(out + (size_t)rowa * 128 + col) = o;
        }
        if (rowb < n) {
            float2 o;
            o.x = elu_f((acc[nt][2] + sb[col]     - mub) * rb * sg[col]     + sbe[col]);
            o.y = elu_f((acc[nt][3] + sb[col + 1] - mub) * rb * sg[col + 1] + sbe[col + 1]);
            *(float2*)(out + (size_t)rowb * 128 + col) = o;
        }
    }
}

// ---------------- gather (warp-per-node, 64-channel) ---------------------------
template <int MODE>
__global__ __launch_bounds__(256) void gather_kernel(
    float* __restrict__ out_param,
    const float* __restrict__ bias, const float* __restrict__ gam,
    const float* __restrict__ bet,
    const float* __restrict__ lw1, const float* __restrict__ lb1,
    const float* __restrict__ g4, const float* __restrict__ be4,
    const float* __restrict__ lw2, const float* __restrict__ lb2,
    int n)
{
    const float* __restrict__ in = (MODE == 0) ? (const float*)g_bufA
                                               : (const float*)g_bufB;
    float* __restrict__ out = (MODE == 0) ? g_bufB
                            : (MODE == 1) ? g_bufA
                                          : out_param;

    __shared__ float s_lw1[64 * 32];
    __shared__ float s_lw2[32 * 32];
    __shared__ float s_lb1[32], s_lb2[32], s_g4[32], s_be4[32];
    if (MODE == 2) {
        int tid = threadIdx.x;
        for (int i = tid; i < 2048; i += 256) s_lw1[i] = lw1[i];
        for (int i = tid; i < 1024; i += 256) s_lw2[i] = lw2[i];
        if (tid < 32) {
            s_lb1[tid] = lb1[tid]; s_lb2[tid] = lb2[tid];
            s_g4[tid] = g4[tid];   s_be4[tid] = be4[tid];
        }
        __syncthreads();
    }
    int lane = threadIdx.x & 31;
    int node = blockIdx.x * 8 + (threadIdx.x >> 5);
    if (node >= n) return;

    int e0 = g_rowptr[node], e1 = g_rowptr[node + 1];
    const float2* inp = (const float2*)in;
    float2 a = inp[(size_t)node * 32 + lane];
    float ax = a.x, ay = a.y;
    int e = e0;
    for (; e + 4 <= e1; e += 4) {
        int i0 = g_col[e], i1 = g_col[e + 1], i2 = g_col[e + 2], i3 = g_col[e + 3];
        float2 v0 = inp[(size_t)i0 * 32 + lane];
        float2 v1 = inp[(size_t)i1 * 32 + lane];
        float2 v2 = inp[(size_t)i2 * 32 + lane];
        float2 v3 = inp[(size_t)i3 * 32 + lane];
        ax += v0.x + v1.x + v2.x + v3.x;
        ay += v0.y + v1.y + v2.y + v3.y;
    }
    for (; e < e1; e++) {
        float2 v = inp[(size_t)g_col[e] * 32 + lane];
        ax += v.x; ay += v.y;
    }
    float dv = g_dinv[node];
    float r0 = dv * ax, r1 = dv * ay;

    if (MODE == 1) {
        ((float2*)out)[(size_t)node * 32 + lane] = make_float2(r0, r1);
        return;
    }

    r0 += bias[lane * 2];
    r1 += bias[lane * 2 + 1];
    float s = r0 + r1, q = r0 * r0 + r1 * r1;
#pragma unroll
    for (int off = 16; off; off >>= 1) {
        s += __shfl_xor_sync(0xffffffffu, s, off);
        q += __shfl_xor_sync(0xffffffffu, q, off);
    }
    float mu = s * (1.f / 64.f);
    float var = q * (1.f / 64.f) - mu * mu;
    float rstd = rsqrtf(var + 1e-5f);
    float y0 = elu_f((r0 - mu) * rstd * gam[lane * 2] + bet[lane * 2]);
    float y1 = elu_f((r1 - mu) * rstd * gam[lane * 2 + 1] + bet[lane * 2 + 1]);

    if (MODE == 0) {
        ((float2*)out)[(size_t)node * 32 + lane] = make_float2(y0 * dv, y1 * dv);
        return;
    }

    float a4 = s_lb1[lane];
#pragma unroll
    for (int k = 0; k < 64; k++) {
        float hv = __shfl_sync(0xffffffffu, (k & 1) ? y1 : y0, k >> 1);
        a4 += hv * s_lw1[k * 32 + lane];
    }
    float s2 = a4, q2 = a4 * a4;
#pragma unroll
    for (int off = 16; off; off >>= 1) {
        s2 += __shfl_xor_sync(0xffffffffu, s2, off);
        q2 += __shfl_xor_sync(0xffffffffu, q2, off);
    }
    float mu2 = s2 * (1.f / 32.f);
    float var2 = q2 * (1.f / 32.f) - mu2 * mu2;
    float rstd2 = rsqrtf(var2 + 1e-5f);
    float z = elu_f((a4 - mu2) * rstd2 * s_g4[lane] + s_be4[lane]);

    float o = s_lb2[lane];
#pragma unroll
    for (int k = 0; k < 32; k++)
        o += __shfl_sync(0xffffffffu, z, k) * s_lw2[k * 32 + lane];
    out[(size_t)node * 32 + lane] = o;
}

// ---------------- launch -------------------------------------------------------
extern "C" void kernel_launch(void* const* d_in, const int* in_sizes, int n_in,
                              void* d_out, int out_size)
{
    const float* x  = (const float*)d_in[0];
    const int*   ei = (const int*)d_in[1];        // int32: JAX downcasts int64
    const float* W1 = (const float*)d_in[2];  const float* b1  = (const float*)d_in[3];
    const float* g1 = (const float*)d_in[4];  const float* be1 = (const float*)d_in[5];
    const float* W2 = (const float*)d_in[6];  const float* b2  = (const float*)d_in[7];
    const float* g2 = (const float*)d_in[8];  const float* be2 = (const float*)d_in[9];
    const float* W3 = (const float*)d_in[10]; const float* b3  = (const float*)d_in[11];
    const float* g3 = (const float*)d_in[12]; const float* be3 = (const float*)d_in[13];
    const float* lw1 = (const float*)d_in[14]; const float* lb1 = (const float*)d_in[15];
    const float* g4  = (const float*)d_in[16]; const float* be4 = (const float*)d_in[17];
    const float* lw2 = (const float*)d_in[18]; const float* lb2 = (const float*)d_in[19];
    float* out = (float*)d_out;

    int n = in_sizes[0] / 128;
    int E = in_sizes[1] / 2;
    int nb = (n + SCAN_CHUNK - 1) / SCAN_CHUNK;

    zero_kernel<<<(n + 255) / 256, 256>>>(n);
    count_kernel<<<(E + 255) / 256, 256>>>(ei, E, n);
    scan_reduce<<<nb, 256>>>(n);
    scan_spine<<<1, 1>>>(n, nb);
    scan_apply<<<nb, 256>>>(n);
    fill_kernel<<<(E + 255) / 256, 256>>>(ei, E, n);

    int gb = (n + 7) / 8;
    int gg = (n + 63) / 64;
    // conv1: g_bufA = (x@W1)*dinv ; g_bufB = elu(LN(dinv*agg + b1))*dinv
    gemm_tf32_k128n64<true><<<gg, 128>>>(x, W1, n);
    gather_kernel<0><<<gb, 256>>>(nullptr, b1, g1, be1,
                                  nullptr, nullptr, nullptr, nullptr, nullptr, nullptr, n);
    // conv2: g_bufA = dinv*(agg g_bufB) ; g_buf128 = elu(LN(g_bufA@W2 + b2))
    gather_kernel<1><<<gb, 256>>>(nullptr, nullptr, nullptr, nullptr,
                                  nullptr, nullptr, nullptr, nullptr, nullptr, nullptr, n);
    gemm2_tf32<<<gg, 128>>>(W2, b2, g2, be2, n);
    // conv3: g_bufB = (g_buf128@W3)*dinv ; head fused into gather -> out
    gemm_tf32_k128n64<false><<<gg, 128>>>(nullptr, W3, n);
    gather_kernel<2><<<gb, 256>>>(out, b3, g3, be3,
                                  lw1, lb1, g4, be4, lw2, lb2, n);
}

// round 8
// speedup vs baseline: 1.1578x; 1.1578x over previous
#include <cuda_runtime.h>
#include <math.h>

#define NODES 100000
#define EMAX  1600000
#define SCAN_CHUNK 2048
#define SCAN_NB ((NODES + SCAN_CHUNK - 1) / SCAN_CHUNK)   // 49

typedef unsigned long long ull;

// ---------------- device scratch ------------------------------------------------
__device__ int   g_deg[NODES];
__device__ int   g_cur[NODES];
__device__ int   g_rowptr[NODES + 1];
__device__ int   g_col[EMAX];
__device__ int   g_blocksum[SCAN_NB];
__device__ int   g_blockoff[SCAN_NB];
__device__ float g_dinv[NODES];
__device__ float g_bufA[(size_t)NODES * 64];
__device__ float g_bufB[(size_t)NODES * 64];
__device__ float g_buf128[(size_t)NODES * 128];

__device__ __forceinline__ float elu_f(float x) { return x > 0.f ? x : expm1f(x); }

// packed fp32x2 FMA (FFMA2) — exact fp32, 2 results per instruction
__device__ __forceinline__ ull pack2(float x, float y) {
    ull r; asm("mov.b64 %0, {%1, %2};" : "=l"(r) : "f"(x), "f"(y)); return r;
}
__device__ __forceinline__ void fma2(ull& c, ull a, ull b) {
    asm("fma.rn.f32x2 %0, %1, %2, %0;" : "+l"(c) : "l"(a), "l"(b));
}
__device__ __forceinline__ float2 unpack2(ull v) {
    float2 r; asm("mov.b64 {%0, %1}, %2;" : "=f"(r.x), "=f"(r.y) : "l"(v)); return r;
}

// ---------------- CSR build (edge_index is int32) ------------------------------
__global__ void zero_kernel(int n) {
    int i = blockIdx.x * blockDim.x + threadIdx.x;
    if (i < n) { g_deg[i] = 0; g_cur[i] = 0; }
}

__global__ void count_kernel(const int* __restrict__ ei, int E, int n) {
    int e = blockIdx.x * blockDim.x + threadIdx.x;
    if (e < E) {
        int d = ei[E + e];
        if ((unsigned)d < (unsigned)n) atomicAdd(&g_deg[d], 1);
    }
}

__global__ __launch_bounds__(256) void scan_reduce(int n) {
    int b = blockIdx.x, t = threadIdx.x;
    int base = b * SCAN_CHUNK + t * 8;
    int s = 0;
#pragma unroll
    for (int i = 0; i < 8; i++) {
        int idx = base + i;
        if (idx < n) s += g_deg[idx];
    }
#pragma unroll
    for (int off = 16; off; off >>= 1)
        s += __shfl_down_sync(0xffffffffu, s, off);
    __shared__ int wsum[8];
    if ((t & 31) == 0) wsum[t >> 5] = s;
    __syncthreads();
    if (t == 0) {
        int tot = 0;
#pragma unroll
        for (int w = 0; w < 8; w++) tot += wsum[w];
        g_blocksum[b] = tot;
    }
}

__global__ void scan_spine(int n, int nb) {
    int run = 0;
    for (int b = 0; b < nb; b++) { g_blockoff[b] = run; run += g_blocksum[b]; }
    g_rowptr[n] = run;
}

__global__ __launch_bounds__(256) void scan_apply(int n) {
    int b = blockIdx.x, t = threadIdx.x;
    int lane = t & 31, wid = t >> 5;
    int base = b * SCAN_CHUNK + t * 8;
    int v[8]; int s = 0;
#pragma unroll
    for (int i = 0; i < 8; i++) {
        int idx = base + i;
        v[i] = (idx < n) ? g_deg[idx] : 0;
        s += v[i];
    }
    int inc = s;
#pragma unroll
    for (int off = 1; off < 32; off <<= 1) {
        int u = __shfl_up_sync(0xffffffffu, inc, off);
        if (lane >= off) inc += u;
    }
    __shared__ int wsum[8];
    if (lane == 31) wsum[wid] = inc;
    __syncthreads();
    int woff = 0;
    for (int w = 0; w < wid; w++) woff += wsum[w];
    int run = g_blockoff[b] + woff + (inc - s);
#pragma unroll
    for (int i = 0; i < 8; i++) {
        int idx = base + i;
        if (idx < n) {
            g_rowptr[idx] = run;
            g_dinv[idx] = rsqrtf((float)v[i] + 1.0f);
        }
        run += v[i];
    }
}

__global__ void fill_kernel(const int* __restrict__ ei, int E, int n) {
    int e = blockIdx.x * blockDim.x + threadIdx.x;
    if (e < E) {
        int s = ei[e];
        int d = ei[E + e];
        if ((unsigned)s < (unsigned)n && (unsigned)d < (unsigned)n) {
            int pos = g_rowptr[d] + atomicAdd(&g_cur[d], 1);
            g_col[pos] = s;
        }
    }
}

// ---------------- GEMM: [N,128] @ [128,64], out *= dinv[row] -------------------
// 256 threads, 64-node tile, thread tile 4 rows x 4 cols (2 packed col-pairs)
template <bool FIRST>
__global__ __launch_bounds__(256) void gemm_128x64(
    const float* __restrict__ Xin, const float* __restrict__ W, int n)
{
    const float* __restrict__ X = FIRST ? Xin : (const float*)g_buf128;
    float* __restrict__ out = FIRST ? g_bufA : g_bufB;

    __shared__ float Ws[128 * 64];   // 32 KB
    __shared__ float Xs[64 * 36];    // 9 KB, padded stride 36
    int tid = threadIdx.x;
    for (int i = tid; i < 128 * 64; i += 256) Ws[i] = W[i];
    int n0 = blockIdx.x * 64;

    int tx = tid & 15, ty = tid >> 4;
    ull acc[4][2];
#pragma unroll
    for (int i = 0; i < 4; i++) { acc[i][0] = 0ull; acc[i][1] = 0ull; }

    for (int kc0 = 0; kc0 < 128; kc0 += 32) {
        __syncthreads();
        for (int i = tid; i < 64 * 8; i += 256) {
            int node = i >> 3, kc = (i & 7) << 2;
            float4 v = make_float4(0.f, 0.f, 0.f, 0.f);
            if (n0 + node < n)
                v = *(const float4*)(X + (size_t)(n0 + node) * 128 + kc0 + kc);
            *(float4*)(Xs + node * 36 + kc) = v;
        }
        __syncthreads();
#pragma unroll
        for (int kk = 0; kk < 32; kk++) {
            int k = kc0 + kk;
            ull pa0 = pack2(Xs[(ty * 4 + 0) * 36 + kk], Xs[(ty * 4 + 0) * 36 + kk]);
            ull pa1 = pack2(Xs[(ty * 4 + 1) * 36 + kk], Xs[(ty * 4 + 1) * 36 + kk]);
            ull pa2 = pack2(Xs[(ty * 4 + 2) * 36 + kk], Xs[(ty * 4 + 2) * 36 + kk]);
            ull pa3 = pack2(Xs[(ty * 4 + 3) * 36 + kk], Xs[(ty * 4 + 3) * 36 + kk]);
            const ull* wp = (const ull*)(Ws + k * 64 + tx * 4);
            ull b01 = wp[0], b23 = wp[1];
            fma2(acc[0][0], pa0, b01); fma2(acc[0][1], pa0, b23);
            fma2(acc[1][0], pa1, b01); fma2(acc[1][1], pa1, b23);
            fma2(acc[2][0], pa2, b01); fma2(acc[2][1], pa2, b23);
            fma2(acc[3][0], pa3, b01); fma2(acc[3][1], pa3, b23);
        }
    }
#pragma unroll
    for (int i = 0; i < 4; i++) {
        int node = n0 + ty * 4 + i;
        if (node < n) {
            float dv = g_dinv[node];
            float2 c01 = unpack2(acc[i][0]);
            float2 c23 = unpack2(acc[i][1]);
            float4 o = make_float4(c01.x * dv, c01.y * dv, c23.x * dv, c23.y * dv);
            *(float4*)(out + (size_t)node * 64 + tx * 4) = o;
        }
    }
}

// ---------------- GEMM2 fused: g_bufA[N,64]@[64,128] + b -> LN -> ELU -> g_buf128
__global__ __launch_bounds__(256) void gemm2_fused(
    const float* __restrict__ W, const float* __restrict__ b,
    const float* __restrict__ g, const float* __restrict__ be, int n)
{
    const float* __restrict__ S = (const float*)g_bufA;
    float* __restrict__ out = g_buf128;

    __shared__ float Ws[64 * 128];   // 32 KB
    __shared__ float Ss[32 * 68];    // 8.7 KB
    __shared__ float sb[128], sg[128], sbe[128];
    int tid = threadIdx.x;
    for (int i = tid; i < 64 * 128; i += 256) Ws[i] = W[i];
    if (tid < 128) { sb[tid] = b[tid]; sg[tid] = g[tid]; sbe[tid] = be[tid]; }
    int n0 = blockIdx.x * 32;
    for (int i = tid; i < 32 * 16; i += 256) {
        int node = i >> 4, kc = (i & 15) << 2;
        float4 v = make_float4(0.f, 0.f, 0.f, 0.f);
        if (n0 + node < n) v = *(const float4*)(S + (size_t)(n0 + node) * 64 + kc);
        *(float4*)(Ss + node * 68 + kc) = v;
    }
    __syncthreads();

    int lane = tid & 31, w = tid >> 5;
    ull acc[4][2];
#pragma unroll
    for (int i = 0; i < 4; i++) { acc[i][0] = 0ull; acc[i][1] = 0ull; }

#pragma unroll 4
    for (int k = 0; k < 64; k++) {
        const ull* wp = (const ull*)(Ws + k * 128 + lane * 4);
        ull b01 = wp[0], b23 = wp[1];
        ull pa0 = pack2(Ss[(w * 4 + 0) * 68 + k], Ss[(w * 4 + 0) * 68 + k]);
        ull pa1 = pack2(Ss[(w * 4 + 1) * 68 + k], Ss[(w * 4 + 1) * 68 + k]);
        ull pa2 = pack2(Ss[(w * 4 + 2) * 68 + k], Ss[(w * 4 + 2) * 68 + k]);
        ull pa3 = pack2(Ss[(w * 4 + 3) * 68 + k], Ss[(w * 4 + 3) * 68 + k]);
        fma2(acc[0][0], pa0, b01); fma2(acc[0][1], pa0, b23);
        fma2(acc[1][0], pa1, b01); fma2(acc[1][1], pa1, b23);
        fma2(acc[2][0], pa2, b01); fma2(acc[2][1], pa2, b23);
        fma2(acc[3][0], pa3, b01); fma2(acc[3][1], pa3, b23);
    }

    int j0 = lane * 4;
#pragma unroll
    for (int i = 0; i < 4; i++) {
        int node = n0 + w * 4 + i;
        float2 c01 = unpack2(acc[i][0]);
        float2 c23 = unpack2(acc[i][1]);
        float v0 = c01.x + sb[j0 + 0];
        float v1 = c01.y + sb[j0 + 1];
        float v2 = c23.x + sb[j0 + 2];
        float v3 = c23.y + sb[j0 + 3];
        float s = v0 + v1 + v2 + v3;
        float q = v0 * v0 + v1 * v1 + v2 * v2 + v3 * v3;
#pragma unroll
        for (int off = 16; off; off >>= 1) {
            s += __shfl_xor_sync(0xffffffffu, s, off);
            q += __shfl_xor_sync(0xffffffffu, q, off);
        }
        float mu = s * (1.f / 128.f);
        float var = q * (1.f / 128.f) - mu * mu;
        float rstd = rsqrtf(var + 1e-5f);
        if (node < n) {
            float4 o;
            o.x = elu_f((v0 - mu) * rstd * sg[j0 + 0] + sbe[j0 + 0]);
            o.y = elu_f((v1 - mu) * rstd * sg[j0 + 1] + sbe[j0 + 1]);
            o.z = elu_f((v2 - mu) * rstd * sg[j0 + 2] + sbe[j0 + 2]);
            o.w = elu_f((v3 - mu) * rstd * sg[j0 + 3] + sbe[j0 + 3]);
            *(float4*)(out + (size_t)node * 128 + j0) = o;
        }
    }
}

// ---------------- gather (warp-per-node, 64-channel) ---------------------------
template <int MODE>
__global__ __launch_bounds__(256) void gather_kernel(
    float* __restrict__ out_param,
    const float* __restrict__ bias, const float* __restrict__ gam,
    const float* __restrict__ bet,
    const float* __restrict__ lw1, const float* __restrict__ lb1,
    const float* __restrict__ g4, const float* __restrict__ be4,
    const float* __restrict__ lw2, const float* __restrict__ lb2,
    int n)
{
    const float* __restrict__ in = (MODE == 0) ? (const float*)g_bufA
                                               : (const float*)g_bufB;
    float* __restrict__ out = (MODE == 0) ? g_bufB
                            : (MODE == 1) ? g_bufA
                                          : out_param;

    __shared__ float s_lw1[64 * 32];
    __shared__ float s_lw2[32 * 32];
    __shared__ float s_lb1[32], s_lb2[32], s_g4[32], s_be4[32];
    if (MODE == 2) {
        int tid = threadIdx.x;
        for (int i = tid; i < 2048; i += 256) s_lw1[i] = lw1[i];
        for (int i = tid; i < 1024; i += 256) s_lw2[i] = lw2[i];
        if (tid < 32) {
            s_lb1[tid] = lb1[tid]; s_lb2[tid] = lb2[tid];
            s_g4[tid] = g4[tid];   s_be4[tid] = be4[tid];
        }
        __syncthreads();
    }
    int lane = threadIdx.x & 31;
    int node = blockIdx.x * 8 + (threadIdx.x >> 5);
    if (node >= n) return;

    int e0 = g_rowptr[node], e1 = g_rowptr[node + 1];
    const float2* inp = (const float2*)in;
    float2 a = inp[(size_t)node * 32 + lane];
    float ax = a.x, ay = a.y;
    int e = e0;
    for (; e + 4 <= e1; e += 4) {
        int i0 = g_col[e], i1 = g_col[e + 1], i2 = g_col[e + 2], i3 = g_col[e + 3];
        float2 v0 = inp[(size_t)i0 * 32 + lane];
        float2 v1 = inp[(size_t)i1 * 32 + lane];
        float2 v2 = inp[(size_t)i2 * 32 + lane];
        float2 v3 = inp[(size_t)i3 * 32 + lane];
        ax += v0.x + v1.x + v2.x + v3.x;
        ay += v0.y + v1.y + v2.y + v3.y;
    }
    for (; e < e1; e++) {
        float2 v = inp[(size_t)g_col[e] * 32 + lane];
        ax += v.x; ay += v.y;
    }
    float dv = g_dinv[node];
    float r0 = dv * ax, r1 = dv * ay;

    if (MODE == 1) {
        ((float2*)out)[(size_t)node * 32 + lane] = make_float2(r0, r1);
        return;
    }

    r0 += bias[lane * 2];
    r1 += bias[lane * 2 + 1];
    float s = r0 + r1, q = r0 * r0 + r1 * r1;
#pragma unroll
    for (int off = 16; off; off >>= 1) {
        s += __shfl_xor_sync(0xffffffffu, s, off);
        q += __shfl_xor_sync(0xffffffffu, q, off);
    }
    float mu = s * (1.f / 64.f);
    float var = q * (1.f / 64.f) - mu * mu;
    float rstd = rsqrtf(var + 1e-5f);
    float y0 = elu_f((r0 - mu) * rstd * gam[lane * 2] + bet[lane * 2]);
    float y1 = elu_f((r1 - mu) * rstd * gam[lane * 2 + 1] + bet[lane * 2 + 1]);

    if (MODE == 0) {
        ((float2*)out)[(size_t)node * 32 + lane] = make_float2(y0 * dv, y1 * dv);
        return;
    }

    float a4 = s_lb1[lane];
#pragma unroll
    for (int k = 0; k < 64; k++) {
        float hv = __shfl_sync(0xffffffffu, (k & 1) ? y1 : y0, k >> 1);
        a4 += hv * s_lw1[k * 32 + lane];
    }
    float s2 = a4, q2 = a4 * a4;
#pragma unroll
    for (int off = 16; off; off >>= 1) {
        s2 += __shfl_xor_sync(0xffffffffu, s2, off);
        q2 += __shfl_xor_sync(0xffffffffu, q2, off);
    }
    float mu2 = s2 * (1.f / 32.f);
    float var2 = q2 * (1.f / 32.f) - mu2 * mu2;
    float rstd2 = rsqrtf(var2 + 1e-5f);
    float z = elu_f((a4 - mu2) * rstd2 * s_g4[lane] + s_be4[lane]);

    float o = s_lb2[lane];
#pragma unroll
    for (int k = 0; k < 32; k++)
        o += __shfl_sync(0xffffffffu, z, k) * s_lw2[k * 32 + lane];
    out[(size_t)node * 32 + lane] = o;
}

// ---------------- launch -------------------------------------------------------
extern "C" void kernel_launch(void* const* d_in, const int* in_sizes, int n_in,
                              void* d_out, int out_size)
{
    const float* x  = (const float*)d_in[0];
    const int*   ei = (const int*)d_in[1];        // int32: JAX downcasts int64
    const float* W1 = (const float*)d_in[2];  const float* b1  = (const float*)d_in[3];
    const float* g1 = (const float*)d_in[4];  const float* be1 = (const float*)d_in[5];
    const float* W2 = (const float*)d_in[6];  const float* b2  = (const float*)d_in[7];
    const float* g2 = (const float*)d_in[8];  const float* be2 = (const float*)d_in[9];
    const float* W3 = (const float*)d_in[10]; const float* b3  = (const float*)d_in[11];
    const float* g3 = (const float*)d_in[12]; const float* be3 = (const float*)d_in[13];
    const float* lw1 = (const float*)d_in[14]; const float* lb1 = (const float*)d_in[15];
    const float* g4  = (const float*)d_in[16]; const float* be4 = (const float*)d_in[17];
    const float* lw2 = (const float*)d_in[18]; const float* lb2 = (const float*)d_in[19];
    float* out = (float*)d_out;

    int n = in_sizes[0] / 128;
    int E = in_sizes[1] / 2;
    int nb = (n + SCAN_CHUNK - 1) / SCAN_CHUNK;

    zero_kernel<<<(n + 255) / 256, 256>>>(n);
    count_kernel<<<(E + 255) / 256, 256>>>(ei, E, n);
    scan_reduce<<<nb, 256>>>(n);
    scan_spine<<<1, 1>>>(n, nb);
    scan_apply<<<nb, 256>>>(n);
    fill_kernel<<<(E + 255) / 256, 256>>>(ei, E, n);

    int gb = (n + 7) / 8;
    // conv1: g_bufA = (x@W1)*dinv ; g_bufB = elu(LN(dinv*agg + b1))*dinv
    gemm_128x64<true><<<(n + 63) / 64, 256>>>(x, W1, n);
    gather_kernel<0><<<gb, 256>>>(nullptr, b1, g1, be1,
                                  nullptr, nullptr, nullptr, nullptr, nullptr, nullptr, n);
    // conv2: g_bufA = dinv*(agg g_bufB) ; g_buf128 = elu(LN(g_bufA@W2 + b2))
    gather_kernel<1><<<gb, 256>>>(nullptr, nullptr, nullptr, nullptr,
                                  nullptr, nullptr, nullptr, nullptr, nullptr, nullptr, n);
    gemm2_fused<<<(n + 31) / 32, 256>>>(W2, b2, g2, be2, n);
    // conv3: g_bufB = (g_buf128@W3)*dinv ; head fused into gather -> out
    gemm_128x64<false><<<(n + 63) / 64, 256>>>(nullptr, W3, n);
    gather_kernel<2><<<gb, 256>>>(out, b3, g3, be3,
                                  lw1, lb1, g4, be4, lw2, lb2, n);
}